// round 2
// baseline (speedup 1.0000x reference)
#include <cuda_runtime.h>
#include <math.h>

#define V     49152
#define BATCH 2
#define M     (BATCH*V)      // 98304
#define DEG   20
#define CIN   128
#define CMID  64

static_assert(M % 768 == 0, "stats grid");

// ---------------- scratch (device globals; no allocation allowed) -------------
__device__ __align__(128) float g_y1[M*CMID];
__device__ __align__(128) float g_h1[M*CMID];
__device__ __align__(128) float g_t1[M*CMID];
__device__ __align__(128) float g_t2[M*CMID];
__device__ __align__(128) float g_y2[M*CMID];
__device__ __align__(128) float g_h2[M*CMID];
__device__ __align__(128) float g_sum[3*128];
__device__ __align__(128) float g_sq [3*128];
__device__ __align__(128) float g_scale[3*128];
__device__ __align__(128) float g_shift[3*128];

// ---------------- init: zero stats accumulators -------------------------------
__global__ void init_stats_kernel() {
    int t = threadIdx.x;
    if (t < 3*128) { g_sum[t] = 0.f; g_sq[t] = 0.f; }
}

// ---------------- GEMM: Y[M,NOUT] = sum_s A_s[M,K] @ W[s*K.., NOUT] + bias ----
// 128 threads/block, one output row per thread, 128 rows per block.
template<int K, int NOUT, int NSRC>
__global__ void gemm_kernel(const float* __restrict__ A0,
                            const float* __restrict__ A1,
                            const float* __restrict__ A2,
                            const float* __restrict__ W,      // [NSRC*K, NOUT]
                            const float* __restrict__ bias,   // [NOUT]
                            float* __restrict__ Y)
{
    extern __shared__ float sm[];
    float* Ws = sm;                         // NSRC*K*NOUT
    float* As = sm + NSRC*K*NOUT;           // 128*(K+1)  (padded rows)
    const int t    = threadIdx.x;           // 0..127
    const int row0 = blockIdx.x * 128;

    // stage full weight block
    const int wf4 = NSRC*K*NOUT/4;
    for (int i = t; i < wf4; i += 128)
        ((float4*)Ws)[i] = ((const float4*)W)[i];

    float acc[NOUT];
    #pragma unroll
    for (int o = 0; o < NOUT; ++o) acc[o] = __ldg(&bias[o]);

    #pragma unroll
    for (int s = 0; s < NSRC; ++s) {
        const float* A = (s == 0) ? A0 : ((s == 1) ? A1 : A2);
        __syncthreads();                    // also covers W-staging on s==0
        // stage A tile: 128 rows x K, padded to K+1 floats/row
        const int nf4 = 128*K/4;
        for (int i = t; i < nf4; i += 128) {
            int r  = i / (K/4);
            int c4 = i % (K/4);
            float4 v = ((const float4*)(A + (size_t)(row0 + r)*K))[c4];
            float* dst = As + r*(K+1) + c4*4;
            dst[0] = v.x; dst[1] = v.y; dst[2] = v.z; dst[3] = v.w;
        }
        __syncthreads();

        const float*  a_row = As + t*(K+1);
        const float4* Wr    = (const float4*)(Ws + s*K*NOUT);
        #pragma unroll 4
        for (int k = 0; k < K; ++k) {
            float a = a_row[k];
            #pragma unroll
            for (int o4 = 0; o4 < NOUT/4; ++o4) {
                float4 b = Wr[k*(NOUT/4) + o4];
                acc[4*o4+0] += a*b.x;
                acc[4*o4+1] += a*b.y;
                acc[4*o4+2] += a*b.z;
                acc[4*o4+3] += a*b.w;
            }
        }
    }

    float4* yo = (float4*)(Y + (size_t)(row0 + t)*NOUT);
    #pragma unroll
    for (int o4 = 0; o4 < NOUT/4; ++o4)
        yo[o4] = make_float4(acc[4*o4+0], acc[4*o4+1], acc[4*o4+2], acc[4*o4+3]);
}

// ---------------- SpMM: warp per row, fixed degree 21 -------------------------
// lane 0..15 -> batch 0 (float4 chunk f4=lane), lane 16..31 -> batch 1.
template<bool CHEB>
__global__ void spmm_kernel(const int*   __restrict__ cols,
                            const float* __restrict__ vals,
                            const float* __restrict__ X,    // [B,V,64]
                            const float* __restrict__ X0,   // CHEB: out = 2*S*X - X0
                            float* __restrict__ Yo)
{
    int warp = (blockIdx.x * blockDim.x + threadIdx.x) >> 5;
    int lane = threadIdx.x & 31;
    if (warp >= V) return;
    const int r  = warp;
    const int b  = lane >> 4;
    const int f4 = lane & 15;
    const float* Xb = X + (size_t)b*V*CMID + f4*4;

    float4 acc = make_float4(0.f, 0.f, 0.f, 0.f);
    // self edge (index r)
    {
        int c = __ldg(&cols[r]); float v = __ldg(&vals[r]);
        float4 xv = *(const float4*)(Xb + (size_t)c*CMID);
        acc.x += v*xv.x; acc.y += v*xv.y; acc.z += v*xv.z; acc.w += v*xv.w;
    }
    const int base = V + r*DEG;
    #pragma unroll
    for (int d = 0; d < DEG; ++d) {
        int c = __ldg(&cols[base+d]); float v = __ldg(&vals[base+d]);
        float4 xv = *(const float4*)(Xb + (size_t)c*CMID);
        acc.x += v*xv.x; acc.y += v*xv.y; acc.z += v*xv.z; acc.w += v*xv.w;
    }
    size_t o = (size_t)b*V*CMID + (size_t)r*CMID + f4*4;
    if (CHEB) {
        float4 x0 = *(const float4*)(X0 + o);
        acc.x = 2.f*acc.x - x0.x; acc.y = 2.f*acc.y - x0.y;
        acc.z = 2.f*acc.z - x0.z; acc.w = 2.f*acc.w - x0.w;
    }
    *(float4*)(Yo + o) = acc;
}

// ---------------- per-channel sum / sumsq over all M rows ---------------------
// grid must be 768; each block reduces M/768 = 128 rows.
template<int C>
__global__ void stats_kernel(const float* __restrict__ Y, float* gs, float* gq)
{
    constexpr int TPC  = 256 / C;     // row groups per block
    constexpr int ROWS = M / 768;     // 128
    int t  = threadIdx.x;
    int c  = t % C;
    int rg = t / C;
    size_t r0 = (size_t)blockIdx.x * ROWS;
    float s = 0.f, q = 0.f;
    for (int r = rg; r < ROWS; r += TPC) {
        float v = Y[(r0 + r)*C + c];
        s += v; q += v*v;
    }
    __shared__ float ss[256], sq[256];
    ss[t] = s; sq[t] = q;
    __syncthreads();
    if (rg == 0) {
        #pragma unroll
        for (int g = 1; g < TPC; ++g) { s += ss[g*C + c]; q += sq[g*C + c]; }
        atomicAdd(&gs[c], s);
        atomicAdd(&gq[c], q);
    }
}

// ---------------- BN finalize: scale/shift per channel ------------------------
__global__ void finalize_kernel(const float* gs, const float* gq,
                                const float* __restrict__ gamma,
                                const float* __restrict__ beta,
                                float* scale, float* shift, int C)
{
    int c = threadIdx.x;
    if (c < C) {
        float mean = gs[c] * (1.f/(float)M);
        float var  = gq[c] * (1.f/(float)M) - mean*mean;
        float sc   = gamma[c] * rsqrtf(var + 1e-5f);
        scale[c] = sc;
        shift[c] = beta[c] - mean*sc;
    }
}

// ---------------- fused BN apply + ReLU ---------------------------------------
template<int C>
__global__ void bnrelu_kernel(const float* __restrict__ Yin,
                              float* __restrict__ H,
                              const float* __restrict__ scale,
                              const float* __restrict__ shift)
{
    int i4 = blockIdx.x * blockDim.x + threadIdx.x;
    constexpr int TOT4 = M*C/4;
    if (i4 >= TOT4) return;
    int c4 = i4 % (C/4);
    float4 v  = ((const float4*)Yin)[i4];
    float4 sc = ((const float4*)scale)[c4];
    float4 sh = ((const float4*)shift)[c4];
    v.x = fmaxf(fmaf(v.x, sc.x, sh.x), 0.f);
    v.y = fmaxf(fmaf(v.y, sc.y, sh.y), 0.f);
    v.z = fmaxf(fmaf(v.z, sc.z, sh.z), 0.f);
    v.w = fmaxf(fmaf(v.w, sc.w, sh.w), 0.f);
    ((float4*)H)[i4] = v;
}

// ------------------------------------------------------------------------------
extern "C" void kernel_launch(void* const* d_in, const int* in_sizes, int n_in,
                              void* d_out, int out_size)
{
    const float* x    = (const float*)d_in[0];
    const int*   cols = (const int*)  d_in[2];
    const float* vals = (const float*)d_in[3];
    const float* W1   = (const float*)d_in[4];
    const float* b1   = (const float*)d_in[5];
    const float* g1   = (const float*)d_in[6];
    const float* be1  = (const float*)d_in[7];
    const float* W2   = (const float*)d_in[8];
    const float* b2   = (const float*)d_in[9];
    const float* g2   = (const float*)d_in[10];
    const float* be2  = (const float*)d_in[11];
    const float* W3   = (const float*)d_in[12];
    const float* b3   = (const float*)d_in[13];
    const float* g3   = (const float*)d_in[14];
    const float* be3  = (const float*)d_in[15];
    float* out = (float*)d_out;

    float *y1, *h1, *t1, *t2, *y2, *h2, *gsum, *gsq, *gscale, *gshift;
    cudaGetSymbolAddress((void**)&y1, g_y1);
    cudaGetSymbolAddress((void**)&h1, g_h1);
    cudaGetSymbolAddress((void**)&t1, g_t1);
    cudaGetSymbolAddress((void**)&t2, g_t2);
    cudaGetSymbolAddress((void**)&y2, g_y2);
    cudaGetSymbolAddress((void**)&h2, g_h2);
    cudaGetSymbolAddress((void**)&gsum,   g_sum);
    cudaGetSymbolAddress((void**)&gsq,    g_sq);
    cudaGetSymbolAddress((void**)&gscale, g_scale);
    cudaGetSymbolAddress((void**)&gshift, g_shift);

    // dynamic smem sizes
    const int smem1 = (1*CIN*CMID  + 128*(CIN+1))  * 4;   // 98816
    const int smem2 = (3*CMID*CMID + 128*(CMID+1)) * 4;   // 82432
    const int smem3 = (1*CMID*CIN  + 128*(CMID+1)) * 4;   // 66048
    cudaFuncSetAttribute(gemm_kernel<CIN,  CMID, 1>, cudaFuncAttributeMaxDynamicSharedMemorySize, smem1);
    cudaFuncSetAttribute(gemm_kernel<CMID, CMID, 3>, cudaFuncAttributeMaxDynamicSharedMemorySize, smem2);
    cudaFuncSetAttribute(gemm_kernel<CMID, CIN,  1>, cudaFuncAttributeMaxDynamicSharedMemorySize, smem3);

    const int GEMM_GRID   = M / 128;        // 768
    const int SPMM_GRID   = V * 32 / 256;   // 6144
    const int BNR_GRID64  = M*CMID/4/256;   // 6144
    const int BNR_GRID128 = M*CIN /4/256;   // 12288

    init_stats_kernel<<<1, 512>>>();

    // ---- layer 1: y1 = x @ W1 + b1 ; BN+ReLU -> h1 ----
    gemm_kernel<CIN, CMID, 1><<<GEMM_GRID, 128, smem1>>>(x, nullptr, nullptr, W1, b1, y1);
    stats_kernel<CMID><<<768, 256>>>(y1, gsum + 0, gsq + 0);
    finalize_kernel<<<1, 128>>>(gsum + 0, gsq + 0, g1, be1, gscale + 0, gshift + 0, CMID);
    bnrelu_kernel<CMID><<<BNR_GRID64, 256>>>(y1, h1, gscale + 0, gshift + 0);

    // ---- layer 2: Chebyshev K=3 ----
    spmm_kernel<false><<<SPMM_GRID, 256>>>(cols, vals, h1, nullptr, t1);          // t1 = S h1
    spmm_kernel<true ><<<SPMM_GRID, 256>>>(cols, vals, t1, h1, t2);               // t2 = 2 S t1 - h1
    gemm_kernel<CMID, CMID, 3><<<GEMM_GRID, 128, smem2>>>(h1, t1, t2, W2, b2, y2);
    stats_kernel<CMID><<<768, 256>>>(y2, gsum + 128, gsq + 128);
    finalize_kernel<<<1, 128>>>(gsum + 128, gsq + 128, g2, be2, gscale + 128, gshift + 128, CMID);
    bnrelu_kernel<CMID><<<BNR_GRID64, 256>>>(y2, h2, gscale + 128, gshift + 128);

    // ---- layer 3: out = BN+ReLU( h2 @ W3 + b3 ) ----
    gemm_kernel<CMID, CIN, 1><<<GEMM_GRID, 128, smem3>>>(h2, nullptr, nullptr, W3, b3, out);
    stats_kernel<CIN><<<768, 256>>>(out, gsum + 256, gsq + 256);
    finalize_kernel<<<1, 128>>>(gsum + 256, gsq + 256, g3, be3, gscale + 256, gshift + 256, CIN);
    bnrelu_kernel<CIN><<<BNR_GRID128, 256>>>(out, out, gscale + 256, gshift + 256);
}

// round 4
// speedup vs baseline: 1.5870x; 1.5870x over previous
#include <cuda_runtime.h>
#include <cuda_bf16.h>
#include <math.h>
#include <stdint.h>

#define V     49152
#define BATCH 2
#define M     (BATCH*V)      // 98304
#define DEG   20
#define CIN   128
#define CMID  64

// ---------------- scratch (device globals; no allocation allowed) -------------
__device__ __align__(128) float g_y1[M*CMID];
__device__ __align__(128) float g_t1[M*CMID];
__device__ __align__(128) float g_t2[M*CMID];
__device__ __align__(128) float g_y2[M*CMID];
__device__ __align__(128) float g_sum[3*128];
__device__ __align__(128) float g_sq [3*128];
__device__ __align__(128) float g_scale[3*128];
__device__ __align__(128) float g_shift[3*128];

// ---------------- init: zero stats accumulators -------------------------------
__global__ void init_stats_kernel() {
    int t = threadIdx.x;
    if (t < 3*128) { g_sum[t] = 0.f; g_sq[t] = 0.f; }
}

// ---------------- mma.sync m16n8k16 bf16 (legacy HMMA path; works on compute_103)
__device__ __forceinline__ void mma16816(float* c, const uint32_t* a, const uint32_t* b) {
    asm volatile(
        "mma.sync.aligned.m16n8k16.row.col.f32.bf16.bf16.f32 "
        "{%0,%1,%2,%3}, {%4,%5,%6,%7}, {%8,%9}, {%0,%1,%2,%3};"
        : "+f"(c[0]), "+f"(c[1]), "+f"(c[2]), "+f"(c[3])
        : "r"(a[0]), "r"(a[1]), "r"(a[2]), "r"(a[3]), "r"(b[0]), "r"(b[1]));
}

__device__ __forceinline__ uint32_t pack2(__nv_bfloat16 a, __nv_bfloat16 b) {
    __nv_bfloat162 h; h.x = a; h.y = b;
    return *reinterpret_cast<uint32_t*>(&h);
}

// ---------------- tensor-core GEMM (HMMA) --------------------------------------
// Y[128-row tile, NOUT] = sum_s A_s[tile, K] @ W[s*K.., NOUT] + bias
// bf16 hi/lo split (hi*hi + hi*lo + lo*hi) with fp32 accumulators.
// BN0: fused BN+ReLU applied to source 0 while staging A.
// smem: A_hi/A_lo [128][KT] bf16 (row stride KT+8), W_hi/W_lo [NOUT][KT] (same stride).
template<int K, int NOUT, int NSRC, bool BN0>
__global__ void __launch_bounds__(256) gemm_mma(
    const float* __restrict__ A0, const float* __restrict__ A1, const float* __restrict__ A2,
    const float* __restrict__ W, const float* __restrict__ bias,
    const float* __restrict__ bsc, const float* __restrict__ bsh,
    float* __restrict__ Y)
{
    constexpr int KT = NSRC*K;
    constexpr int SA = KT + 8;                  // padded stride (elements) -> conflict-free frags
    constexpr int ABYTES = 128*SA*2;
    constexpr int WBYTES = NOUT*SA*2;

    extern __shared__ char smc[];
    __nv_bfloat16* Ah = (__nv_bfloat16*)(smc);
    __nv_bfloat16* Al = (__nv_bfloat16*)(smc + ABYTES);
    __nv_bfloat16* Wh = (__nv_bfloat16*)(smc + 2*ABYTES);
    __nv_bfloat16* Wl = (__nv_bfloat16*)(smc + 2*ABYTES + WBYTES);

    const int t    = threadIdx.x;
    const int wid  = t >> 5, lane = t & 31;
    const int row0 = blockIdx.x * 128;
    const int g    = lane >> 2, tg = lane & 3;

    // ---- stage W transposed: Wt[n][kt] = W[kt][n], hi/lo ----
    for (int i = t; i < KT*NOUT; i += 256) {
        int n = i % NOUT, k = i / NOUT;
        float w = W[i];
        __nv_bfloat16 h = __float2bfloat16(w);
        Wh[n*SA + k] = h;
        Wl[n*SA + k] = __float2bfloat16(w - __bfloat162float(h));
    }

    // ---- stage A: [128][KT] hi/lo, optional fused BN+ReLU on source 0 ----
    #pragma unroll
    for (int s = 0; s < NSRC; ++s) {
        const float* A = (s == 0) ? A0 : ((s == 1) ? A1 : A2);
        for (int i = t; i < 128*(K/4); i += 256) {
            int r = i / (K/4), c4 = i % (K/4);
            float4 v = *(const float4*)(A + (size_t)(row0 + r)*K + c4*4);
            if (BN0 && s == 0) {
                float4 sc = *(const float4*)(bsc + c4*4);
                float4 sh = *(const float4*)(bsh + c4*4);
                v.x = fmaxf(fmaf(v.x, sc.x, sh.x), 0.f);
                v.y = fmaxf(fmaf(v.y, sc.y, sh.y), 0.f);
                v.z = fmaxf(fmaf(v.z, sc.z, sh.z), 0.f);
                v.w = fmaxf(fmaf(v.w, sc.w, sh.w), 0.f);
            }
            __nv_bfloat16 hx = __float2bfloat16(v.x), hy = __float2bfloat16(v.y);
            __nv_bfloat16 hz = __float2bfloat16(v.z), hw = __float2bfloat16(v.w);
            int col = s*K + c4*4;
            uint32_t* dh = (uint32_t*)(Ah + r*SA + col);
            uint32_t* dl = (uint32_t*)(Al + r*SA + col);
            dh[0] = pack2(hx, hy);
            dh[1] = pack2(hz, hw);
            dl[0] = pack2(__float2bfloat16(v.x - __bfloat162float(hx)),
                          __float2bfloat16(v.y - __bfloat162float(hy)));
            dl[1] = pack2(__float2bfloat16(v.z - __bfloat162float(hz)),
                          __float2bfloat16(v.w - __bfloat162float(hw)));
        }
    }
    __syncthreads();

    // ---- compute: warp owns rows [wid*16, wid*16+16), all NOUT cols ----
    constexpr int NB = NOUT/8;
    float acc[NB][4];
    #pragma unroll
    for (int nb = 0; nb < NB; ++nb)
        acc[nb][0] = acc[nb][1] = acc[nb][2] = acc[nb][3] = 0.f;

    const int rb = wid*16;
    const __nv_bfloat16* arow0 = Ah + (rb + g)*SA;        // hi rows g / g+8
    const __nv_bfloat16* arow8 = Ah + (rb + g + 8)*SA;
    const __nv_bfloat16* lrow0 = Al + (rb + g)*SA;
    const __nv_bfloat16* lrow8 = Al + (rb + g + 8)*SA;

    #pragma unroll 2
    for (int kk = 0; kk < KT/16; ++kk) {
        const int kb = kk*16 + tg*2;
        uint32_t ah[4], al[4];
        ah[0] = *(const uint32_t*)(arow0 + kb);
        ah[1] = *(const uint32_t*)(arow8 + kb);
        ah[2] = *(const uint32_t*)(arow0 + kb + 8);
        ah[3] = *(const uint32_t*)(arow8 + kb + 8);
        al[0] = *(const uint32_t*)(lrow0 + kb);
        al[1] = *(const uint32_t*)(lrow8 + kb);
        al[2] = *(const uint32_t*)(lrow0 + kb + 8);
        al[3] = *(const uint32_t*)(lrow8 + kb + 8);
        #pragma unroll
        for (int nb = 0; nb < NB; ++nb) {
            const __nv_bfloat16* wrow = Wh + (nb*8 + g)*SA;
            const __nv_bfloat16* wlo  = Wl + (nb*8 + g)*SA;
            uint32_t bh[2], bl[2];
            bh[0] = *(const uint32_t*)(wrow + kb);
            bh[1] = *(const uint32_t*)(wrow + kb + 8);
            bl[0] = *(const uint32_t*)(wlo  + kb);
            bl[1] = *(const uint32_t*)(wlo  + kb + 8);
            mma16816(acc[nb], ah, bh);   // hi*hi
            mma16816(acc[nb], ah, bl);   // hi*lo
            mma16816(acc[nb], al, bh);   // lo*hi
        }
    }

    // ---- store: rows rb+g / rb+g+8, cols nb*8 + tg*2 (+bias) ----
    float* y0 = Y + (size_t)(row0 + rb + g)*NOUT;
    float* y8 = Y + (size_t)(row0 + rb + g + 8)*NOUT;
    #pragma unroll
    for (int nb = 0; nb < NB; ++nb) {
        int c = nb*8 + tg*2;
        float2 bb = __ldg((const float2*)(bias + c));
        *(float2*)(y0 + c) = make_float2(acc[nb][0] + bb.x, acc[nb][1] + bb.y);
        *(float2*)(y8 + c) = make_float2(acc[nb][2] + bb.x, acc[nb][3] + bb.y);
    }
}

// ---------------- SpMM: warp per row, fixed degree 21 -------------------------
// GBN: apply BN+ReLU (sc/sh) to gathered X elements on the fly.
// CHEB: out = 2*acc - bnrelu(X0).
template<bool GBN, bool CHEB>
__global__ void spmm_kernel(const int*   __restrict__ cols,
                            const float* __restrict__ vals,
                            const float* __restrict__ X,
                            const float* __restrict__ X0,
                            const float* __restrict__ sc_g,
                            const float* __restrict__ sh_g,
                            float* __restrict__ Yo)
{
    int warp = (blockIdx.x * blockDim.x + threadIdx.x) >> 5;
    int lane = threadIdx.x & 31;
    if (warp >= V) return;
    const int r  = warp;
    const int b  = lane >> 4;
    const int f4 = lane & 15;
    const float* Xb = X + (size_t)b*V*CMID + f4*4;

    float4 sc = make_float4(0,0,0,0), sh = make_float4(0,0,0,0);
    if (GBN || CHEB) {
        sc = *(const float4*)(sc_g + f4*4);
        sh = *(const float4*)(sh_g + f4*4);
    }

    float4 acc = make_float4(0.f, 0.f, 0.f, 0.f);
    {
        int c = __ldg(&cols[r]); float v = __ldg(&vals[r]);
        float4 xv = *(const float4*)(Xb + (size_t)c*CMID);
        if (GBN) {
            xv.x = fmaxf(fmaf(xv.x, sc.x, sh.x), 0.f);
            xv.y = fmaxf(fmaf(xv.y, sc.y, sh.y), 0.f);
            xv.z = fmaxf(fmaf(xv.z, sc.z, sh.z), 0.f);
            xv.w = fmaxf(fmaf(xv.w, sc.w, sh.w), 0.f);
        }
        acc.x += v*xv.x; acc.y += v*xv.y; acc.z += v*xv.z; acc.w += v*xv.w;
    }
    const int base = V + r*DEG;
    #pragma unroll
    for (int d = 0; d < DEG; ++d) {
        int c = __ldg(&cols[base+d]); float v = __ldg(&vals[base+d]);
        float4 xv = *(const float4*)(Xb + (size_t)c*CMID);
        if (GBN) {
            xv.x = fmaxf(fmaf(xv.x, sc.x, sh.x), 0.f);
            xv.y = fmaxf(fmaf(xv.y, sc.y, sh.y), 0.f);
            xv.z = fmaxf(fmaf(xv.z, sc.z, sh.z), 0.f);
            xv.w = fmaxf(fmaf(xv.w, sc.w, sh.w), 0.f);
        }
        acc.x += v*xv.x; acc.y += v*xv.y; acc.z += v*xv.z; acc.w += v*xv.w;
    }
    size_t o = (size_t)b*V*CMID + (size_t)r*CMID + f4*4;
    if (CHEB) {
        float4 x0 = *(const float4*)(X0 + o);
        x0.x = fmaxf(fmaf(x0.x, sc.x, sh.x), 0.f);
        x0.y = fmaxf(fmaf(x0.y, sc.y, sh.y), 0.f);
        x0.z = fmaxf(fmaf(x0.z, sc.z, sh.z), 0.f);
        x0.w = fmaxf(fmaf(x0.w, sc.w, sh.w), 0.f);
        acc.x = 2.f*acc.x - x0.x; acc.y = 2.f*acc.y - x0.y;
        acc.z = 2.f*acc.z - x0.z; acc.w = 2.f*acc.w - x0.w;
    }
    *(float4*)(Yo + o) = acc;
}

// ---------------- per-channel sum / sumsq over all M rows ---------------------
template<int C>
__global__ void stats_kernel(const float* __restrict__ Y, float* gs, float* gq)
{
    constexpr int TPC  = 256 / C;
    constexpr int ROWS = M / 768;
    int t  = threadIdx.x;
    int c  = t % C;
    int rg = t / C;
    size_t r0 = (size_t)blockIdx.x * ROWS;
    float s = 0.f, q = 0.f;
    for (int r = rg; r < ROWS; r += TPC) {
        float v = Y[(r0 + r)*C + c];
        s += v; q += v*v;
    }
    __shared__ float ss[256], sq[256];
    ss[t] = s; sq[t] = q;
    __syncthreads();
    if (rg == 0) {
        #pragma unroll
        for (int g = 1; g < TPC; ++g) { s += ss[g*C + c]; q += sq[g*C + c]; }
        atomicAdd(&gs[c], s);
        atomicAdd(&gq[c], q);
    }
}

// ---------------- BN finalize ---------------------------------------------------
__global__ void finalize_kernel(const float* gs, const float* gq,
                                const float* __restrict__ gamma,
                                const float* __restrict__ beta,
                                float* scale, float* shift, int C)
{
    int c = threadIdx.x;
    if (c < C) {
        float mean = gs[c] * (1.f/(float)M);
        float var  = gq[c] * (1.f/(float)M) - mean*mean;
        float s    = gamma[c] * rsqrtf(var + 1e-5f);
        scale[c] = s;
        shift[c] = beta[c] - mean*s;
    }
}

// ---------------- fused BN apply + ReLU (final layer only) --------------------
template<int C>
__global__ void bnrelu_kernel(const float* __restrict__ Yin,
                              float* __restrict__ H,
                              const float* __restrict__ scale,
                              const float* __restrict__ shift)
{
    int i4 = blockIdx.x * blockDim.x + threadIdx.x;
    constexpr int TOT4 = M*C/4;
    if (i4 >= TOT4) return;
    int c4 = i4 % (C/4);
    float4 v  = ((const float4*)Yin)[i4];
    float4 sc = ((const float4*)scale)[c4];
    float4 sh = ((const float4*)shift)[c4];
    v.x = fmaxf(fmaf(v.x, sc.x, sh.x), 0.f);
    v.y = fmaxf(fmaf(v.y, sc.y, sh.y), 0.f);
    v.z = fmaxf(fmaf(v.z, sc.z, sh.z), 0.f);
    v.w = fmaxf(fmaf(v.w, sc.w, sh.w), 0.f);
    ((float4*)H)[i4] = v;
}

// ------------------------------------------------------------------------------
extern "C" void kernel_launch(void* const* d_in, const int* in_sizes, int n_in,
                              void* d_out, int out_size)
{
    const float* x    = (const float*)d_in[0];
    const int*   cols = (const int*)  d_in[2];
    const float* vals = (const float*)d_in[3];
    const float* W1   = (const float*)d_in[4];
    const float* b1   = (const float*)d_in[5];
    const float* g1   = (const float*)d_in[6];
    const float* be1  = (const float*)d_in[7];
    const float* W2   = (const float*)d_in[8];
    const float* b2   = (const float*)d_in[9];
    const float* g2   = (const float*)d_in[10];
    const float* be2  = (const float*)d_in[11];
    const float* W3   = (const float*)d_in[12];
    const float* b3   = (const float*)d_in[13];
    const float* g3   = (const float*)d_in[14];
    const float* be3  = (const float*)d_in[15];
    float* out = (float*)d_out;

    float *y1, *t1, *t2, *y2, *gsum, *gsq, *gscale, *gshift;
    cudaGetSymbolAddress((void**)&y1, g_y1);
    cudaGetSymbolAddress((void**)&t1, g_t1);
    cudaGetSymbolAddress((void**)&t2, g_t2);
    cudaGetSymbolAddress((void**)&y2, g_y2);
    cudaGetSymbolAddress((void**)&gsum,   g_sum);
    cudaGetSymbolAddress((void**)&gsq,    g_sq);
    cudaGetSymbolAddress((void**)&gscale, g_scale);
    cudaGetSymbolAddress((void**)&gshift, g_shift);

    // dynamic smem: 2*A + 2*W bf16 tiles, stride KT+8
    const int smem1 = 2*(128*(128+8)*2) + 2*(64*(128+8)*2);    // 104448
    const int smem2 = 2*(128*(192+8)*2) + 2*(64*(192+8)*2);    // 153600
    const int smem3 = 2*(128*(64+8)*2)  + 2*(128*(64+8)*2);    //  73728
    cudaFuncSetAttribute(gemm_mma<128, 64, 1, false>, cudaFuncAttributeMaxDynamicSharedMemorySize, smem1);
    cudaFuncSetAttribute(gemm_mma< 64, 64, 3, true >, cudaFuncAttributeMaxDynamicSharedMemorySize, smem2);
    cudaFuncSetAttribute(gemm_mma< 64,128, 1, true >, cudaFuncAttributeMaxDynamicSharedMemorySize, smem3);

    const int GEMM_GRID   = M / 128;        // 768
    const int SPMM_GRID   = V * 32 / 256;   // 6144
    const int BNR_GRID128 = M*CIN/4/256;    // 12288

    init_stats_kernel<<<1, 512>>>();

    // ---- layer 1: y1 = x @ W1 + b1 (raw); BN stats ----
    gemm_mma<128, 64, 1, false><<<GEMM_GRID, 256, smem1>>>(x, nullptr, nullptr, W1, b1, nullptr, nullptr, y1);
    stats_kernel<CMID><<<768, 256>>>(y1, gsum + 0, gsq + 0);
    finalize_kernel<<<1, 128>>>(gsum + 0, gsq + 0, g1, be1, gscale + 0, gshift + 0, CMID);

    // ---- layer 2: Chebyshev K=3, h1 = bnrelu(y1) materialized on the fly ----
    spmm_kernel<true , false><<<SPMM_GRID, 256>>>(cols, vals, y1, nullptr, gscale + 0, gshift + 0, t1); // t1 = S h1
    spmm_kernel<false, true ><<<SPMM_GRID, 256>>>(cols, vals, t1, y1,      gscale + 0, gshift + 0, t2); // t2 = 2 S t1 - h1
    gemm_mma<64, 64, 3, true><<<GEMM_GRID, 256, smem2>>>(y1, t1, t2, W2, b2, gscale + 0, gshift + 0, y2);
    stats_kernel<CMID><<<768, 256>>>(y2, gsum + 128, gsq + 128);
    finalize_kernel<<<1, 128>>>(gsum + 128, gsq + 128, g2, be2, gscale + 128, gshift + 128, CMID);

    // ---- layer 3: out = bnrelu( bnrelu(y2) @ W3 + b3 ) ----
    gemm_mma<64, 128, 1, true><<<GEMM_GRID, 256, smem3>>>(y2, nullptr, nullptr, W3, b3, gscale + 128, gshift + 128, out);
    stats_kernel<CIN><<<768, 256>>>(out, gsum + 256, gsq + 256);
    finalize_kernel<<<1, 128>>>(gsum + 256, gsq + 256, g3, be3, gscale + 256, gshift + 256, CIN);
    bnrelu_kernel<CIN><<<BNR_GRID128, 256>>>(out, out, gscale + 256, gshift + 256);
}